// round 5
// baseline (speedup 1.0000x reference)
#include <cuda_runtime.h>
#include <cuda_bf16.h>
#include <math.h>
#include <stdint.h>

// NCE loss: scores(16384x104) = inp(16384x512) @ noise_emb^T via HMMA bf16.
// Grid=128 CTAs x 512 thr (16 warps). Warps 0-7: token-stripe x n-tiles 0-6;
// warps 8-15: same stripes x n-tiles 7-12 (A reread hits L2). Target dots
// spread over all 16 warps. B resident in smem (bf16, swizzled for ldmatrix).

#define E      512
#define NRR    100
#define NP     104          // 13 * 8
#define NT     13
#define TPB    512
#define GRID1  128
#define NTOK   16384

#define SM_B     0          // 104 rows * 1024B
#define SM_SC    106496     // 104 floats
#define SM_RED   106912     // 16 floats
#define SM_FLAG  106976
#define SM_TOTAL 107008

__device__ float        g_partials[GRID1];
__device__ unsigned int g_counter;

struct __align__(16) u64x2 { unsigned long long x, y; };

__device__ __forceinline__ unsigned long long fma2(unsigned long long a,
                                                   unsigned long long b,
                                                   unsigned long long c) {
    unsigned long long d;
    asm("fma.rn.f32x2 %0, %1, %2, %3;" : "=l"(d) : "l"(a), "l"(b), "l"(c));
    return d;
}
__device__ __forceinline__ float pairsum(unsigned long long u) {
    float lo, hi;
    asm("mov.b64 {%0, %1}, %2;" : "=f"(lo), "=f"(hi) : "l"(u));
    return lo + hi;
}
__device__ __forceinline__ float softplus_fast(float x) {
    return fmaxf(x, 0.0f) + __logf(1.0f + __expf(-fabsf(x)));
}
__device__ __forceinline__ uint32_t smem_u32(const void* p) {
    uint32_t a;
    asm("{ .reg .u64 t; cvta.to.shared.u64 t, %1; cvt.u32.u64 %0, t; }"
        : "=r"(a) : "l"(p));
    return a;
}
__device__ __forceinline__ uint32_t bf2(float lo, float hi) {
    uint32_t r;
    asm("cvt.rn.bf16x2.f32 %0, %1, %2;" : "=r"(r) : "f"(hi), "f"(lo));
    return r;
}
__device__ __forceinline__ void mma16816(float* d,
        uint32_t a0, uint32_t a1, uint32_t a2, uint32_t a3,
        uint32_t b0, uint32_t b1) {
    asm volatile("mma.sync.aligned.m16n8k16.row.col.f32.bf16.bf16.f32 "
        "{%0,%1,%2,%3}, {%4,%5,%6,%7}, {%8,%9}, {%0,%1,%2,%3};"
        : "+f"(d[0]), "+f"(d[1]), "+f"(d[2]), "+f"(d[3])
        : "r"(a0), "r"(a1), "r"(a2), "r"(a3), "r"(b0), "r"(b1));
}

__global__ void __launch_bounds__(TPB, 1)
nce_hmma(const float* __restrict__ inp,
         const float* __restrict__ emb,
         const float* __restrict__ bias,
         const float* __restrict__ logn,
         const int*   __restrict__ target,
         const int*   __restrict__ noise_idx,
         float csub, float* __restrict__ out)
{
    extern __shared__ char smem[];
    const uint32_t sb = smem_u32(smem);
    const int tid = threadIdx.x, warp = tid >> 5, lane = tid & 31;
    const int gid = lane >> 2, ctg = lane & 3;
    const int stripe = warp & 7;           // token stripe (16 rows)
    const int half   = warp >> 3;          // n-tile half: 0 -> tiles 0-6, 1 -> 7-12
    const int ntl    = half ? 6 : 7;       // tiles this warp owns
    const int tbase  = half * 7;           // first tile index
    float* sC    = (float*)(smem + SM_SC);
    float* sRed  = (float*)(smem + SM_RED);
    int*   sFlag = (int*)(smem + SM_FLAG);
    const int tokBase = blockIdx.x * 128;

    // ---- stage B: 104 x 512 bf16, 16B chunks XOR-swizzled per row
    for (int i = tid; i < NP * 64; i += TPB) {
        int n = i >> 6, c = i & 63;
        uint4 pk = make_uint4(0u, 0u, 0u, 0u);
        if (n < NRR) {
            int nid = noise_idx[n];
            const float4* r = (const float4*)(emb + (size_t)nid * E) + (c << 1);
            float4 v0 = r[0], v1 = r[1];
            pk.x = bf2(v0.x, v0.y); pk.y = bf2(v0.z, v0.w);
            pk.z = bf2(v1.x, v1.y); pk.w = bf2(v1.z, v1.w);
        }
        *(uint4*)(smem + SM_B + n * 1024 + ((c ^ (n & 7)) << 4)) = pk;
    }
    if (tid < NP) {
        float cv = -INFINITY;              // pad cols 100..103 -> softplus 0
        if (tid < NRR) {
            int nid = noise_idx[tid];
            cv = bias[nid] - logn[nid] - csub;
        }
        sC[tid] = cv;
    }
    __syncthreads();

    float myLoss = 0.0f;

    // ---- target dots: 8 tokens per warp, pairs for MLP
    #pragma unroll 1
    for (int i = 0; i < 8; i += 2) {
        int t0 = tokBase + warp * 8 + i;
        int tg0 = target[t0], tg1 = target[t0 + 1];
        const u64x2* i0 = (const u64x2*)(inp + (size_t)t0 * E);
        const u64x2* i1 = (const u64x2*)(inp + (size_t)(t0 + 1) * E);
        const u64x2* e0 = (const u64x2*)(emb + (size_t)tg0 * E);
        const u64x2* e1 = (const u64x2*)(emb + (size_t)tg1 * E);
        unsigned long long A0 = 0ull, A1 = 0ull;
        #pragma unroll
        for (int q = 0; q < 4; ++q) {
            u64x2 a = i0[lane + q * 32], b = e0[lane + q * 32];
            u64x2 c = i1[lane + q * 32], d = e1[lane + q * 32];
            A0 = fma2(a.x, b.x, A0); A0 = fma2(a.y, b.y, A0);
            A1 = fma2(c.x, d.x, A1); A1 = fma2(c.y, d.y, A1);
        }
        float s0 = pairsum(A0), s1 = pairsum(A1);
        #pragma unroll
        for (int d = 16; d >= 1; d >>= 1) {
            s0 += __shfl_xor_sync(0xffffffffu, s0, d);
            s1 += __shfl_xor_sync(0xffffffffu, s1, d);
        }
        if (lane == 0) {
            myLoss += softplus_fast(-(s0 + bias[tg0] - logn[tg0] - csub));
            myLoss += softplus_fast(-(s1 + bias[tg1] - logn[tg1] - csub));
        }
    }

    // ---- GEMM: 16 token rows x (6 or 7) n-tiles, K=512 (32 k-steps)
    float acc[7][4];
    #pragma unroll
    for (int t = 0; t < 7; ++t)
        #pragma unroll
        for (int r = 0; r < 4; ++r) acc[t][r] = 0.0f;

    // ldmatrix slots: 3 x4 slots (tiles tbase..tbase+5) + 1 x2 slot (tile tbase+6, half0 only)
    int nb[4], m7[4];
    #pragma unroll
    for (int p = 0; p < 3; ++p) {
        int n = (tbase + 2 * p + (lane >> 4)) * 8 + (lane & 7);
        nb[p] = n * 1024; m7[p] = n & 7;
    }
    { int n = (tbase + 6) * 8 + (lane & 7); nb[3] = n * 1024; m7[3] = n & 7; }
    const int khB = (lane >> 3) & 1;

    const float* aR0 = inp + (size_t)(tokBase + stripe * 16 + gid) * E + ctg * 2;
    const float* aR1 = aR0 + 8 * E;

    float2 f0 = *(const float2*)(aR0);
    float2 f1 = *(const float2*)(aR1);
    float2 f2 = *(const float2*)(aR0 + 8);
    float2 f3 = *(const float2*)(aR1 + 8);

    #pragma unroll 4
    for (int ks = 0; ks < 32; ++ks) {
        uint32_t a0 = bf2(f0.x, f0.y), a1 = bf2(f1.x, f1.y);
        uint32_t a2 = bf2(f2.x, f2.y), a3 = bf2(f3.x, f3.y);
        if (ks < 31) {
            const float* p0 = aR0 + (ks + 1) * 16;
            const float* p1 = aR1 + (ks + 1) * 16;
            f0 = *(const float2*)(p0);     f1 = *(const float2*)(p1);
            f2 = *(const float2*)(p0 + 8); f3 = *(const float2*)(p1 + 8);
        }
        const int cb = ks * 2 + khB;
        #pragma unroll
        for (int p = 0; p < 3; ++p) {
            uint32_t b0, b1, b2, b3;
            uint32_t addr = sb + (uint32_t)(nb[p] + ((cb ^ m7[p]) << 4));
            asm volatile("ldmatrix.sync.aligned.m8n8.x4.shared.b16 "
                         "{%0,%1,%2,%3}, [%4];"
                         : "=r"(b0), "=r"(b1), "=r"(b2), "=r"(b3) : "r"(addr));
            mma16816(acc[2 * p],     a0, a1, a2, a3, b0, b1);
            mma16816(acc[2 * p + 1], a0, a1, a2, a3, b2, b3);
        }
        if (half == 0) {
            uint32_t b0, b1;
            uint32_t addr = sb + (uint32_t)(nb[3] + ((cb ^ m7[3]) << 4));
            asm volatile("ldmatrix.sync.aligned.m8n8.x2.shared.b16 "
                         "{%0,%1}, [%2];"
                         : "=r"(b0), "=r"(b1) : "r"(addr));
            mma16816(acc[6], a0, a1, a2, a3, b0, b1);
        }
    }

    // ---- epilogue: softplus over this warp's score tiles
    #pragma unroll
    for (int t = 0; t < 7; ++t) {
        if (t >= ntl) break;
        float c0 = sC[(tbase + t) * 8 + ctg * 2];
        float c1 = sC[(tbase + t) * 8 + ctg * 2 + 1];
        myLoss += softplus_fast(acc[t][0] + c0);
        myLoss += softplus_fast(acc[t][1] + c1);
        myLoss += softplus_fast(acc[t][2] + c0);
        myLoss += softplus_fast(acc[t][3] + c1);
    }

    // ---- block reduce (16 warps)
    #pragma unroll
    for (int d = 16; d >= 1; d >>= 1)
        myLoss += __shfl_xor_sync(0xffffffffu, myLoss, d);
    if (lane == 0) sRed[warp] = myLoss;
    __syncthreads();

    // ---- cross-block: last block reduces
    if (tid == 0) {
        float s = 0.f;
        #pragma unroll
        for (int w = 0; w < 16; ++w) s += sRed[w];
        g_partials[blockIdx.x] = s;
        __threadfence();
        unsigned n = atomicAdd(&g_counter, 1u);
        sFlag[0] = (n == GRID1 - 1) ? 1 : 0;
    }
    __syncthreads();
    if (sFlag[0]) {
        float v = (tid < GRID1) ? g_partials[tid] : 0.f;
        #pragma unroll
        for (int d = 16; d >= 1; d >>= 1)
            v += __shfl_xor_sync(0xffffffffu, v, d);
        if (lane == 0) sRed[warp] = v;
        __syncthreads();
        if (tid == 0) {
            float s = 0.f;
            #pragma unroll
            for (int w = 0; w < 16; ++w) s += sRed[w];
            out[0] = s * (1.0f / (float)NTOK);
            g_counter = 0u;                 // reset for next graph replay
        }
    }
}

extern "C" void kernel_launch(void* const* d_in, const int* in_sizes, int n_in,
                              void* d_out, int out_size) {
    (void)in_sizes; (void)n_in; (void)out_size;
    const float* inp       = (const float*)d_in[0];
    const float* emb       = (const float*)d_in[1];
    const float* bias      = (const float*)d_in[2];
    const float* logn      = (const float*)d_in[3];
    const int*   target    = (const int*)d_in[4];
    const int*   noise_idx = (const int*)d_in[5];

    float csub = logf(50257.0f) + logf(100.0f);   // NORM_TERM + LOG_NR

    cudaFuncSetAttribute(nce_hmma, cudaFuncAttributeMaxDynamicSharedMemorySize, SM_TOTAL);
    nce_hmma<<<GRID1, TPB, SM_TOTAL>>>(inp, emb, bias, logn, target, noise_idx,
                                       csub, (float*)d_out);
}

// round 6
// speedup vs baseline: 1.1503x; 1.1503x over previous
#include <cuda_runtime.h>
#include <cuda_bf16.h>
#include <math.h>
#include <stdint.h>

// NCE loss: scores(16384x104) = inp(16384x512) @ noise_emb^T via HMMA bf16.
// Grid=128 CTAs x 256 thr. B (104x512 bf16) resident in smem (swizzled for
// ldmatrix). A staged f32 through smem via cp.async, triple-buffered k64
// chunks; target dots folded into the chunk loop (input slice read from the
// A chunk, emb rows gathered with batched MLP, hidden behind MMAs).

#define E      512
#define NRR    100
#define NP     104          // 13 * 8
#define NT     13
#define TPB    256
#define GRID1  128
#define NTOK   16384

#define AROWB  272          // 68 floats row stride (bank-conflict pad)
#define ABUF   34816        // 128 * 272
#define SM_B   0            // 104 rows * 1024B = 106496
#define SM_SC  106496       // 104 floats
#define SM_RED 106912       // 8 floats
#define SM_FLAG 106976
#define SM_A    107008      // 3 x 34816
#define SM_TOTAL (SM_A + 3 * ABUF)   // 211456

__device__ float        g_partials[GRID1];
__device__ unsigned int g_counter;

__device__ __forceinline__ float softplus_fast(float x) {
    return fmaxf(x, 0.0f) + __logf(1.0f + __expf(-fabsf(x)));
}
__device__ __forceinline__ uint32_t smem_u32(const void* p) {
    uint32_t a;
    asm("{ .reg .u64 t; cvta.to.shared.u64 t, %1; cvt.u32.u64 %0, t; }"
        : "=r"(a) : "l"(p));
    return a;
}
__device__ __forceinline__ uint32_t bf2(float lo, float hi) {
    uint32_t r;
    asm("cvt.rn.bf16x2.f32 %0, %1, %2;" : "=r"(r) : "f"(hi), "f"(lo));
    return r;
}
__device__ __forceinline__ void mma16816(float* d,
        uint32_t a0, uint32_t a1, uint32_t a2, uint32_t a3,
        uint32_t b0, uint32_t b1) {
    asm volatile("mma.sync.aligned.m16n8k16.row.col.f32.bf16.bf16.f32 "
        "{%0,%1,%2,%3}, {%4,%5,%6,%7}, {%8,%9}, {%0,%1,%2,%3};"
        : "+f"(d[0]), "+f"(d[1]), "+f"(d[2]), "+f"(d[3])
        : "r"(a0), "r"(a1), "r"(a2), "r"(a3), "r"(b0), "r"(b1));
}

__global__ void __launch_bounds__(TPB, 1)
nce_hmma(const float* __restrict__ inp,
         const float* __restrict__ emb,
         const float* __restrict__ bias,
         const float* __restrict__ logn,
         const int*   __restrict__ target,
         const int*   __restrict__ noise_idx,
         float csub, float* __restrict__ out)
{
    extern __shared__ char smem[];
    const uint32_t sb = smem_u32(smem);
    const int tid = threadIdx.x, warp = tid >> 5, lane = tid & 31;
    const int gid = lane >> 2, ctg = lane & 3;
    float* sC    = (float*)(smem + SM_SC);
    float* sRed  = (float*)(smem + SM_RED);
    int*   sFlag = (int*)(smem + SM_FLAG);
    const int tokBase = blockIdx.x * 128;

    // ---- cp.async stage of A chunk c (128 rows x 64 f32) into buf c%3
    auto stageA = [&](int c) {
        char* dst = smem + SM_A + (c % 3) * ABUF;
        const float* src = inp + (size_t)tokBase * E + c * 64;
        #pragma unroll
        for (int i = 0; i < 8; ++i) {
            int idx = tid + i * TPB;            // 2048 16B transfers
            int row = idx >> 4, cp = idx & 15;
            uint32_t sa = sb + (uint32_t)(SM_A + (c % 3) * ABUF + row * AROWB + cp * 16);
            const float* ga = src + (size_t)row * E + cp * 4;
            asm volatile("cp.async.cg.shared.global [%0], [%1], 16;"
                         :: "r"(sa), "l"(ga));
        }
        (void)dst;
        asm volatile("cp.async.commit_group;");
    };

    stageA(0);
    stageA(1);

    // ---- stage B: 104 x 512 bf16, 16B chunks XOR-swizzled per row
    for (int i = tid; i < NP * 64; i += TPB) {
        int n = i >> 6, c = i & 63;
        uint4 pk = make_uint4(0u, 0u, 0u, 0u);
        if (n < NRR) {
            int nid = noise_idx[n];
            const float4* r = (const float4*)(emb + (size_t)nid * E) + (c << 1);
            float4 v0 = r[0], v1 = r[1];
            pk.x = bf2(v0.x, v0.y); pk.y = bf2(v0.z, v0.w);
            pk.z = bf2(v1.x, v1.y); pk.w = bf2(v1.z, v1.w);
        }
        *(uint4*)(smem + SM_B + n * 1024 + ((c ^ (n & 7)) << 4)) = pk;
    }
    if (tid < NP) {
        float cv = -INFINITY;              // pad cols 100..103 -> softplus 0
        if (tid < NRR) {
            int nid = noise_idx[tid];
            cv = bias[nid] - logn[nid] - csub;
        }
        sC[tid] = cv;
    }

    // target ids for this warp's 16 tokens (lane i < 16 holds token i)
    int tgts = 0;
    if (lane < 16) tgts = target[tokBase + warp * 16 + lane];

    __syncthreads();

    // ---- GEMM accumulators + target partials
    float acc[NT][4];
    #pragma unroll
    for (int t = 0; t < NT; ++t)
        #pragma unroll
        for (int r = 0; r < 4; ++r) acc[t][r] = 0.0f;
    float tacc[16];
    #pragma unroll
    for (int i = 0; i < 16; ++i) tacc[i] = 0.0f;

    // ldmatrix slots (R4-proven): 6 x4 slots (tiles 0..11) + 1 x2 slot (tile 12)
    int nb[7], m7[7];
    #pragma unroll
    for (int p = 0; p < 6; ++p) {
        int n = (2 * p + (lane >> 4)) * 8 + (lane & 7);
        nb[p] = n * 1024; m7[p] = n & 7;
    }
    { int n = 96 + (lane & 7); nb[6] = n * 1024; m7[6] = n & 7; }
    const int khB = (lane >> 3) & 1;
    const int row0 = warp * 16 + gid, row1 = row0 + 8;

    #pragma unroll 1
    for (int c = 0; c < 8; ++c) {
        if (c < 7) asm volatile("cp.async.wait_group 1;" ::: "memory");
        else       asm volatile("cp.async.wait_group 0;" ::: "memory");
        __syncthreads();

        const char* Ab = smem + SM_A + (c % 3) * ABUF;

        float2 ebuf[8];
        #pragma unroll
        for (int i = 0; i < 8; ++i) {
            int tg = __shfl_sync(0xffffffffu, tgts, i);
            ebuf[i] = *(const float2*)(emb + (size_t)tg * E + c * 64 + lane * 2);
        }

        #pragma unroll
        for (int kl = 0; kl < 4; ++kl) {
            const char* a0p = Ab + row0 * AROWB + (kl * 16 + ctg * 2) * 4;
            const char* a1p = Ab + row1 * AROWB + (kl * 16 + ctg * 2) * 4;
            float2 f0 = *(const float2*)a0p;
            float2 f2 = *(const float2*)(a0p + 32);
            float2 f1 = *(const float2*)a1p;
            float2 f3 = *(const float2*)(a1p + 32);
            uint32_t a0 = bf2(f0.x, f0.y), a1 = bf2(f1.x, f1.y);
            uint32_t a2 = bf2(f2.x, f2.y), a3 = bf2(f3.x, f3.y);

            const int cb = (c * 4 + kl) * 2 + khB;
            #pragma unroll
            for (int p = 0; p < 6; ++p) {
                uint32_t b0, b1, b2, b3;
                uint32_t addr = sb + (uint32_t)(nb[p] + ((cb ^ m7[p]) << 4));
                asm volatile("ldmatrix.sync.aligned.m8n8.x4.shared.b16 "
                             "{%0,%1,%2,%3}, [%4];"
                             : "=r"(b0), "=r"(b1), "=r"(b2), "=r"(b3) : "r"(addr));
                mma16816(acc[2 * p],     a0, a1, a2, a3, b0, b1);
                mma16816(acc[2 * p + 1], a0, a1, a2, a3, b2, b3);
            }
            {
                uint32_t b0, b1;
                uint32_t addr = sb + (uint32_t)(nb[6] + ((cb ^ m7[6]) << 4));
                asm volatile("ldmatrix.sync.aligned.m8n8.x2.shared.b16 "
                             "{%0,%1}, [%2];"
                             : "=r"(b0), "=r"(b1) : "r"(addr));
                mma16816(acc[12], a0, a1, a2, a3, b0, b1);
            }

            if (kl == 1) {       // consume batch 0, issue batch 1 (hidden by MMAs)
                #pragma unroll
                for (int i = 0; i < 8; ++i) {
                    float2 in = *(const float2*)(Ab + (warp * 16 + i) * AROWB + lane * 8);
                    tacc[i] = fmaf(in.y, ebuf[i].y, fmaf(in.x, ebuf[i].x, tacc[i]));
                }
                #pragma unroll
                for (int i = 0; i < 8; ++i) {
                    int tg = __shfl_sync(0xffffffffu, tgts, i + 8);
                    ebuf[i] = *(const float2*)(emb + (size_t)tg * E + c * 64 + lane * 2);
                }
            }
        }
        #pragma unroll
        for (int i = 0; i < 8; ++i) {
            float2 in = *(const float2*)(Ab + (warp * 16 + i + 8) * AROWB + lane * 8);
            tacc[i + 8] = fmaf(in.y, ebuf[i].y, fmaf(in.x, ebuf[i].x, tacc[i + 8]));
        }

        __syncthreads();                 // all warps done with buf (c-1)%3 region
        if (c + 2 < 8) stageA(c + 2);    // write buf (c+2)%3 (free since iter c-1)
    }

    float myLoss = 0.0f;

    // ---- target scores: reduce 16 per-lane partials, lane i keeps token i
    float mineT = 0.0f;
    #pragma unroll
    for (int i = 0; i < 16; ++i) {
        float s = tacc[i];
        #pragma unroll
        for (int d = 16; d >= 1; d >>= 1)
            s += __shfl_xor_sync(0xffffffffu, s, d);
        if (lane == i) mineT = s;
    }
    if (lane < 16) {
        float xt = mineT + bias[tgts] - logn[tgts] - csub;
        myLoss += softplus_fast(-xt);
    }

    // ---- epilogue: softplus over all 128x104 scores
    #pragma unroll
    for (int nt = 0; nt < NT; ++nt) {
        float c0 = sC[nt * 8 + ctg * 2];
        float c1 = sC[nt * 8 + ctg * 2 + 1];
        myLoss += softplus_fast(acc[nt][0] + c0);
        myLoss += softplus_fast(acc[nt][1] + c1);
        myLoss += softplus_fast(acc[nt][2] + c0);
        myLoss += softplus_fast(acc[nt][3] + c1);
    }

    // ---- block reduce
    #pragma unroll
    for (int d = 16; d >= 1; d >>= 1)
        myLoss += __shfl_xor_sync(0xffffffffu, myLoss, d);
    if (lane == 0) sRed[warp] = myLoss;
    __syncthreads();

    // ---- cross-block: last block reduces (single kernel)
    if (tid == 0) {
        float s = 0.f;
        #pragma unroll
        for (int w = 0; w < 8; ++w) s += sRed[w];
        g_partials[blockIdx.x] = s;
        __threadfence();
        unsigned n = atomicAdd(&g_counter, 1u);
        sFlag[0] = (n == GRID1 - 1) ? 1 : 0;
    }
    __syncthreads();
    if (sFlag[0]) {
        float v = (tid < GRID1) ? g_partials[tid] : 0.f;
        #pragma unroll
        for (int d = 16; d >= 1; d >>= 1)
            v += __shfl_xor_sync(0xffffffffu, v, d);
        if (lane == 0) sRed[warp] = v;
        __syncthreads();
        if (tid == 0) {
            float s = 0.f;
            #pragma unroll
            for (int w = 0; w < 8; ++w) s += sRed[w];
            out[0] = s * (1.0f / (float)NTOK);
            g_counter = 0u;                 // reset for next graph replay
        }
    }
}

extern "C" void kernel_launch(void* const* d_in, const int* in_sizes, int n_in,
                              void* d_out, int out_size) {
    (void)in_sizes; (void)n_in; (void)out_size;
    const float* inp       = (const float*)d_in[0];
    const float* emb       = (const float*)d_in[1];
    const float* bias      = (const float*)d_in[2];
    const float* logn      = (const float*)d_in[3];
    const int*   target    = (const int*)d_in[4];
    const int*   noise_idx = (const int*)d_in[5];

    float csub = logf(50257.0f) + logf(100.0f);   // NORM_TERM + LOG_NR

    cudaFuncSetAttribute(nce_hmma, cudaFuncAttributeMaxDynamicSharedMemorySize, SM_TOTAL);
    nce_hmma<<<GRID1, TPB, SM_TOTAL>>>(inp, emb, bias, logn, target, noise_idx,
                                       csub, (float*)d_out);
}